// round 11
// baseline (speedup 1.0000x reference)
#include <cuda_runtime.h>
#include <math.h>
#include <stdint.h>

// ---------------- problem constants ----------------
#define T_TOK 2048
#define HDIM  2048
#define FB    8192
#define NE    8
#define FE    1024
#define TOPK  2
#define NPAIR (T_TOK * TOPK)

// ---------------- scratch ----------------
__device__ float g_G   [(size_t)T_TOK * FB];
__device__ float g_Hb  [(size_t)T_TOK * FB];     // tf32-rounded (fed to down GEMM)
__device__ float g_base[(size_t)T_TOK * HDIM];
__device__ float g_EG  [(size_t)NPAIR * FE];
__device__ float g_HE  [(size_t)NPAIR * FE];     // tf32-rounded
__device__ float g_pout[(size_t)NPAIR * HDIM];
__device__ int   g_cnt[NE];
__device__ int   g_off[NE + 1];
__device__ int   g_cur[NE];
__device__ int   g_tokexp[T_TOK * TOPK];
__device__ float g_tokw  [T_TOK * TOPK];
__device__ int   g_pairtok[NPAIR];
__device__ float g_pairw  [NPAIR];
__device__ int   g_tokpair[T_TOK * TOPK];
__device__ float g_c[T_TOK];

// tf32-preconverted operands
__device__ float g_xc  [(size_t)T_TOK * HDIM];
__device__ float g_wgc [(size_t)FB * HDIM];
__device__ float g_wuc [(size_t)FB * HDIM];
__device__ float g_wdc [(size_t)HDIM * FB];
__device__ float g_wegc[(size_t)NE * FE * HDIM];
__device__ float g_weuc[(size_t)NE * FE * HDIM];
__device__ float g_wedc[(size_t)NE * HDIM * FE];

// ---------------- helpers ----------------
__device__ __forceinline__ uint32_t smem_u32(const void* p) {
    uint32_t a;
    asm("{ .reg .u64 t; cvta.to.shared.u64 t, %1; cvt.u32.u64 %0, t; }" : "=r"(a) : "l"(p));
    return a;
}
__device__ __forceinline__ float tf32r(float f) {
    uint32_t u;
    asm("cvt.rna.tf32.f32 %0, %1;" : "=r"(u) : "f"(f));
    return __uint_as_float(u);
}
__device__ __forceinline__ void mma_tf32(float c[4], const uint32_t a[4], const uint32_t b[2]) {
    asm volatile(
        "mma.sync.aligned.m16n8k8.row.col.f32.tf32.tf32.f32 "
        "{%0,%1,%2,%3}, {%4,%5,%6,%7}, {%8,%9}, {%0,%1,%2,%3};\n"
        : "+f"(c[0]), "+f"(c[1]), "+f"(c[2]), "+f"(c[3])
        : "r"(a[0]), "r"(a[1]), "r"(a[2]), "r"(a[3]), "r"(b[0]), "r"(b[1]));
}
#define LDSM_X4(r, addr) \
    asm volatile("ldmatrix.sync.aligned.m8n8.x4.shared.b16 {%0,%1,%2,%3}, [%4];" \
        : "=r"((r)[0]), "=r"((r)[1]), "=r"((r)[2]), "=r"((r)[3]) : "r"(addr))
#define CP_ASYNC16(dst, src, sz) \
    asm volatile("cp.async.cg.shared.global [%0], [%1], 16, %2;" \
        :: "r"(dst), "l"(src), "r"(sz) : "memory")
#define CP_COMMIT() asm volatile("cp.async.commit_group;" ::: "memory")
#define CP_WAIT1()  asm volatile("cp.async.wait_group 1;" ::: "memory")

// ---------------- batched tf32 conversion prepass ----------------
struct CvtArgs {
    const float* src[7];
    float* dst[7];
    int n4[7];
};
__global__ void cvt_all_kernel(CvtArgs a) {
    int seg = blockIdx.y;
    const float4* src = reinterpret_cast<const float4*>(a.src[seg]);
    float4* dst = reinterpret_cast<float4*>(a.dst[seg]);
    int n4 = a.n4[seg];
    int stride = gridDim.x * blockDim.x;
    for (int i = blockIdx.x * blockDim.x + threadIdx.x; i < n4; i += stride) {
        float4 v = src[i];
        v.x = tf32r(v.x); v.y = tf32r(v.y); v.z = tf32r(v.z); v.w = tf32r(v.w);
        dst[i] = v;
    }
}

// ---------------- small kernels (fp32-exact routing) ----------------
__global__ void zero_counts_kernel() {
    int i = threadIdx.x;
    if (i < NE) g_cnt[i] = 0;
}

__global__ void router_kernel(const float* __restrict__ x,
                              const float* __restrict__ rw,
                              const float* __restrict__ alpha) {
    int t = blockIdx.x;
    int tid = threadIdx.x;
    int w = tid >> 5;
    int lane = tid & 31;
    __shared__ float lg[NE];

    float s = 0.f;
    const float* xr = x + (size_t)t * HDIM;
    const float* wr = rw + (size_t)w * HDIM;
    for (int h = lane; h < HDIM; h += 32) s += xr[h] * wr[h];
    #pragma unroll
    for (int o = 16; o > 0; o >>= 1) s += __shfl_down_sync(0xffffffffu, s, o);
    if (lane == 0) lg[w] = s;
    __syncthreads();

    if (tid == 0) {
        float v0 = -1e30f, v1 = -1e30f;
        int i0 = 0, i1 = 0;
        #pragma unroll
        for (int e = 0; e < NE; e++) {
            float v = lg[e];
            if (v > v0) { v1 = v0; i1 = i0; v0 = v; i0 = e; }
            else if (v > v1) { v1 = v; i1 = e; }
        }
        float e1 = expf(v1 - v0);
        float inv = 1.f / (1.f + e1);
        float wa0 = inv * alpha[i0];
        float wa1 = e1 * inv * alpha[i1];
        g_tokexp[2 * t + 0] = i0;
        g_tokexp[2 * t + 1] = i1;
        g_tokw[2 * t + 0] = wa0;
        g_tokw[2 * t + 1] = wa1;
        g_c[t] = 1.f - wa0 - wa1;
        atomicAdd(&g_cnt[i0], 1);
        atomicAdd(&g_cnt[i1], 1);
    }
}

__global__ void scan_kernel() {
    if (threadIdx.x == 0) {
        int acc = 0;
        for (int e = 0; e < NE; e++) {
            g_off[e] = acc;
            g_cur[e] = acc;
            acc += g_cnt[e];
        }
        g_off[NE] = acc;
    }
}

__global__ void scatter_kernel() {
    int t = blockIdx.x * blockDim.x + threadIdx.x;
    if (t >= T_TOK) return;
    #pragma unroll
    for (int s = 0; s < TOPK; s++) {
        int e = g_tokexp[2 * t + s];
        int pos = atomicAdd(&g_cur[e], 1);
        g_pairtok[pos] = t;
        g_pairw[pos] = g_tokw[2 * t + s];
        g_tokpair[2 * t + s] = pos;
    }
}

// ---------------- cp.async 3-stage tf32 GEMM, BM=128 BN=256, 512 threads ----------
// C[m,n] = sum_k A[m,k]*B[n,k]; BK=32, 128B rows, swizzled.
// Swizzle: elem(row, c) at byte row*128 + (((c>>2) ^ (row&7))<<4) + (c&3)*4.
// MODE 0: C=acc; MODE 1: C=silu(aux)*acc; MODE 2: C=acc*rowscale[row]
// RND: round output to tf32 (intermediates feeding another GEMM)
#define BN 256
#define A_TILE 16384                  // 128x32 f32
#define B_TILE 32768                  // 256x32 f32
#define STAGE_B (A_TILE + B_TILE)     // 48KB
#define NSTAGE 3
#define SMEM_TOTAL (NSTAGE * STAGE_B) // 144KB

template <int MODE, bool GROUPED, bool GATHER, bool RND>
__global__ void __launch_bounds__(512, 1)
gemm_cp(const float* __restrict__ A,
        const float* __restrict__ Bb,
        float* __restrict__ C,
        const float* __restrict__ aux,
        const float* __restrict__ rowscale,
        const int* __restrict__ offs,
        const int* __restrict__ gidx,
        int M, int N, int K) {
    extern __shared__ __align__(128) char smem[];

    int rstart, rend;
    const float* B = Bb;
    if (GROUPED) {
        int e = blockIdx.z;
        rstart = offs[e];
        rend = offs[e + 1];
        B += (size_t)e * N * K;
    } else {
        rstart = 0;
        rend = M;
    }
    int rowBase = rstart + blockIdx.y * 128;
    if (rowBase >= rend) return;
    int colBase = blockIdx.x * BN;

    uint32_t sb = smem_u32(smem);
    int tid = threadIdx.x;
    int wid = tid >> 5, lane = tid & 31;
    int warp_m = wid & 1;     // 2 warps over M (64 rows)
    int warp_n = wid >> 1;    // 8 warps over N (32 cols)
    int g = lane >> 2, tg = lane & 3;

    // loader assignments: A 2 chunks, B 4 chunks of 16B per thread
    int larow[2], lac4[2], aidx[2];
    uint32_t lasoff[2], asz[2];
    #pragma unroll
    for (int j = 0; j < 2; j++) {
        int f = tid + j * 512;
        larow[j] = f >> 3;
        lac4[j] = f & 7;
        lasoff[j] = (uint32_t)(larow[j] * 128 + ((lac4[j] ^ (larow[j] & 7)) << 4));
        int grow = rowBase + larow[j];
        bool v = (grow < rend);
        asz[j] = v ? 16u : 0u;
        aidx[j] = v ? (GATHER ? gidx[grow] : grow) : 0;
    }
    int lbrow[4], lbc4[4];
    uint32_t lbsoff[4];
    #pragma unroll
    for (int j = 0; j < 4; j++) {
        int f = tid + j * 512;
        lbrow[j] = f >> 3;
        lbc4[j] = f & 7;
        lbsoff[j] = (uint32_t)(lbrow[j] * 128 + ((lbc4[j] ^ (lbrow[j] & 7)) << 4));
    }

    // ldmatrix address components (verified mapping)
    int la7 = lane & 7;
    int lav = lane >> 4;              // A x4: k-chunk selector
    int bhi = (lane >> 3) & 1;        // B: k-chunk selector within pair
    int bnadd = (lane >> 4) * 8;      // B: +8 n-rows for matrices 2,3
    uint32_t a_row0 = (uint32_t)(warp_m * 64 + la7 + (((lane >> 3) & 1) ? 8 : 0));
    uint32_t b_row0 = (uint32_t)(warp_n * 32 + bnadd + la7);

    float acc[4][4][4];
    #pragma unroll
    for (int mt = 0; mt < 4; mt++)
        #pragma unroll
        for (int nt = 0; nt < 4; nt++)
            #pragma unroll
            for (int r = 0; r < 4; r++) acc[mt][nt][r] = 0.f;

    int NC = K / 32;

    auto issue = [&](int stage, int k0) {
        uint32_t abase = sb + stage * STAGE_B;
        uint32_t bbase = abase + A_TILE;
        #pragma unroll
        for (int j = 0; j < 2; j++) {
            const float* src = A + (size_t)aidx[j] * K + k0 + lac4[j] * 4;
            CP_ASYNC16(abase + lasoff[j], src, asz[j]);
        }
        #pragma unroll
        for (int j = 0; j < 4; j++) {
            const float* src = B + (size_t)(colBase + lbrow[j]) * K + k0 + lbc4[j] * 4;
            CP_ASYNC16(bbase + lbsoff[j], src, 16u);
        }
    };

    issue(0, 0);
    CP_COMMIT();
    if (NC > 1) issue(1, 32);
    CP_COMMIT();

    for (int i = 0; i < NC; i++) {
        CP_WAIT1();
        __syncthreads();
        if (i + 2 < NC) issue((i + 2) % NSTAGE, (i + 2) * 32);
        CP_COMMIT();

        uint32_t abase = sb + (i % NSTAGE) * STAGE_B;
        uint32_t bbase = abase + A_TILE;
        #pragma unroll
        for (int ks = 0; ks < 4; ks++) {
            uint32_t af[4][4], bf2[2][4];
            #pragma unroll
            for (int mt = 0; mt < 4; mt++) {
                uint32_t addr = abase + (a_row0 + mt * 16) * 128 +
                                ((uint32_t)((ks * 2 + lav) ^ la7) << 4);
                LDSM_X4(af[mt], addr);
            }
            #pragma unroll
            for (int np = 0; np < 2; np++) {
                uint32_t addr = bbase + (b_row0 + (uint32_t)(np * 16)) * 128 +
                                ((uint32_t)((ks * 2 + bhi) ^ la7) << 4);
                LDSM_X4(bf2[np], addr);
            }
            #pragma unroll
            for (int mt = 0; mt < 4; mt++)
                #pragma unroll
                for (int nt = 0; nt < 4; nt++)
                    mma_tf32(acc[mt][nt], af[mt], &bf2[nt >> 1][(nt & 1) * 2]);
        }
    }

    // epilogue: fragment -> float2 stores
    #pragma unroll
    for (int mt = 0; mt < 4; mt++) {
        #pragma unroll
        for (int half = 0; half < 2; half++) {
            int grow = rowBase + warp_m * 64 + mt * 16 + g + half * 8;
            if (grow >= rend) continue;
            float rs = (MODE == 2) ? rowscale[grow] : 0.f;
            #pragma unroll
            for (int nt = 0; nt < 4; nt++) {
                int col = colBase + warp_n * 32 + nt * 8 + tg * 2;
                size_t idx = (size_t)grow * N + col;
                float v0 = acc[mt][nt][half * 2 + 0];
                float v1 = acc[mt][nt][half * 2 + 1];
                float2 r;
                if (MODE == 0) {
                    r = make_float2(v0, v1);
                } else if (MODE == 1) {
                    float2 gg = *reinterpret_cast<const float2*>(aux + idx);
                    float s0 = gg.x / (1.f + __expf(-gg.x));
                    float s1 = gg.y / (1.f + __expf(-gg.y));
                    r = make_float2(s0 * v0, s1 * v1);
                } else {
                    r = make_float2(rs * v0, rs * v1);
                }
                if (RND) { r.x = tf32r(r.x); r.y = tf32r(r.y); }
                *reinterpret_cast<float2*>(C + idx) = r;
            }
        }
    }
}

// ---------------- combine ----------------
__global__ void combine_kernel(float* __restrict__ out) {
    int t = blockIdx.x;
    int i = threadIdx.x;  // 0..511 (H/4)
    int p0 = g_tokpair[2 * t + 0];
    int p1 = g_tokpair[2 * t + 1];
    float ct = g_c[t];
    const float4* b4 = reinterpret_cast<const float4*>(g_base) + (size_t)t * (HDIM / 4);
    const float4* q0 = reinterpret_cast<const float4*>(g_pout) + (size_t)p0 * (HDIM / 4);
    const float4* q1 = reinterpret_cast<const float4*>(g_pout) + (size_t)p1 * (HDIM / 4);
    float4 b = b4[i], a0 = q0[i], a1 = q1[i];
    float4 r;
    r.x = ct * b.x + a0.x + a1.x;
    r.y = ct * b.y + a0.y + a1.y;
    r.z = ct * b.z + a0.z + a1.z;
    r.w = ct * b.w + a0.w + a1.w;
    reinterpret_cast<float4*>(out)[(size_t)t * (HDIM / 4) + i] = r;
}

// ---------------- launch ----------------
extern "C" void kernel_launch(void* const* d_in, const int* in_sizes, int n_in,
                              void* d_out, int out_size) {
    const float* x   = (const float*)d_in[0];
    const float* wg  = (const float*)d_in[1];
    const float* wu  = (const float*)d_in[2];
    const float* wd  = (const float*)d_in[3];
    const float* rw  = (const float*)d_in[4];
    const float* weg = (const float*)d_in[5];
    const float* weu = (const float*)d_in[6];
    const float* wed = (const float*)d_in[7];
    const float* alp = (const float*)d_in[8];
    float* out = (float*)d_out;

    float *pG, *pHb, *pBase, *pEG, *pHE, *pPout, *pPairw;
    float *pXc, *pWgc, *pWuc, *pWdc, *pWegc, *pWeuc, *pWedc;
    int *pOff, *pPairtok;
    cudaGetSymbolAddress((void**)&pG, g_G);
    cudaGetSymbolAddress((void**)&pHb, g_Hb);
    cudaGetSymbolAddress((void**)&pBase, g_base);
    cudaGetSymbolAddress((void**)&pEG, g_EG);
    cudaGetSymbolAddress((void**)&pHE, g_HE);
    cudaGetSymbolAddress((void**)&pPout, g_pout);
    cudaGetSymbolAddress((void**)&pPairw, g_pairw);
    cudaGetSymbolAddress((void**)&pOff, g_off);
    cudaGetSymbolAddress((void**)&pPairtok, g_pairtok);
    cudaGetSymbolAddress((void**)&pXc, g_xc);
    cudaGetSymbolAddress((void**)&pWgc, g_wgc);
    cudaGetSymbolAddress((void**)&pWuc, g_wuc);
    cudaGetSymbolAddress((void**)&pWdc, g_wdc);
    cudaGetSymbolAddress((void**)&pWegc, g_wegc);
    cudaGetSymbolAddress((void**)&pWeuc, g_weuc);
    cudaGetSymbolAddress((void**)&pWedc, g_wedc);

    cudaFuncSetAttribute(gemm_cp<0, false, false, false>, cudaFuncAttributeMaxDynamicSharedMemorySize, SMEM_TOTAL);
    cudaFuncSetAttribute(gemm_cp<1, false, false, true>,  cudaFuncAttributeMaxDynamicSharedMemorySize, SMEM_TOTAL);
    cudaFuncSetAttribute(gemm_cp<0, true, true, false>,   cudaFuncAttributeMaxDynamicSharedMemorySize, SMEM_TOTAL);
    cudaFuncSetAttribute(gemm_cp<1, true, true, true>,    cudaFuncAttributeMaxDynamicSharedMemorySize, SMEM_TOTAL);
    cudaFuncSetAttribute(gemm_cp<2, true, false, false>,  cudaFuncAttributeMaxDynamicSharedMemorySize, SMEM_TOTAL);

    // 0) batched tf32 prepass (one launch; 2072 CTAs = 14 waves of 148)
    {
        CvtArgs a;
        a.src[0] = x;   a.dst[0] = pXc;   a.n4[0] = (T_TOK * HDIM) / 4;
        a.src[1] = wg;  a.dst[1] = pWgc;  a.n4[1] = (FB * HDIM) / 4;
        a.src[2] = wu;  a.dst[2] = pWuc;  a.n4[2] = (FB * HDIM) / 4;
        a.src[3] = wd;  a.dst[3] = pWdc;  a.n4[3] = (HDIM * FB) / 4;
        a.src[4] = weg; a.dst[4] = pWegc; a.n4[4] = (NE * FE * HDIM) / 4;
        a.src[5] = weu; a.dst[5] = pWeuc; a.n4[5] = (NE * FE * HDIM) / 4;
        a.src[6] = wed; a.dst[6] = pWedc; a.n4[6] = (NE * HDIM * FE) / 4;
        dim3 grid(296, 7, 1);
        cvt_all_kernel<<<grid, 256>>>(a);
    }

    // 1) routing (fp32-exact, uses original x)
    zero_counts_kernel<<<1, 32>>>();
    router_kernel<<<T_TOK, 256>>>(x, rw, alp);
    scan_kernel<<<1, 1>>>();
    scatter_kernel<<<T_TOK / 256, 256>>>();

    // 2) base MLP
    dim3 gBaseFF(FB / BN, T_TOK / 128, 1);
    gemm_cp<0, false, false, false><<<gBaseFF, 512, SMEM_TOTAL>>>(pXc, pWgc, pG, nullptr, nullptr, nullptr, nullptr,
                                                                  T_TOK, FB, HDIM);
    gemm_cp<1, false, false, true><<<gBaseFF, 512, SMEM_TOTAL>>>(pXc, pWuc, pHb, pG, nullptr, nullptr, nullptr,
                                                                 T_TOK, FB, HDIM);
    dim3 gBaseDown(HDIM / BN, T_TOK / 128, 1);
    gemm_cp<0, false, false, false><<<gBaseDown, 512, SMEM_TOTAL>>>(pHb, pWdc, pBase, nullptr, nullptr, nullptr, nullptr,
                                                                    T_TOK, HDIM, FB);

    // 3) expert MLPs (grouped, gathered)
    dim3 gExpFF(FE / BN, 16, NE);
    gemm_cp<0, true, true, false><<<gExpFF, 512, SMEM_TOTAL>>>(pXc, pWegc, pEG, nullptr, nullptr, pOff, pPairtok,
                                                               NPAIR, FE, HDIM);
    gemm_cp<1, true, true, true><<<gExpFF, 512, SMEM_TOTAL>>>(pXc, pWeuc, pHE, pEG, nullptr, pOff, pPairtok,
                                                              NPAIR, FE, HDIM);
    dim3 gExpDown(HDIM / BN, 16, NE);
    gemm_cp<2, true, false, false><<<gExpDown, 512, SMEM_TOTAL>>>(pHE, pWedc, pPout, nullptr, pPairw, pOff, nullptr,
                                                                  NPAIR, HDIM, FE);

    // 4) combine
    combine_kernel<<<T_TOK, HDIM / 4>>>(out);
}

// round 15
// speedup vs baseline: 1.9087x; 1.9087x over previous
#include <cuda_runtime.h>
#include <cuda_fp16.h>
#include <math.h>
#include <stdint.h>

// ---------------- problem constants ----------------
#define T_TOK 2048
#define HDIM  2048
#define FB    8192
#define NE    8
#define FE    1024
#define TOPK  2
#define NPAIR (T_TOK * TOPK)

// ---------------- scratch ----------------
__device__ float  g_G   [(size_t)T_TOK * FB];     // gate preact (fp32, aux for silu)
__device__ __half g_Hbh [(size_t)T_TOK * FB];     // base hidden (fp16, feeds down GEMM)
__device__ float  g_base[(size_t)T_TOK * HDIM];
__device__ float  g_EG  [(size_t)NPAIR * FE];
__device__ __half g_HEh [(size_t)NPAIR * FE];
__device__ float  g_pout[(size_t)NPAIR * HDIM];
__device__ int    g_cnt[NE];
__device__ int    g_off[NE + 1];
__device__ int    g_cur[NE];
__device__ int    g_tokexp[T_TOK * TOPK];
__device__ float  g_tokw  [T_TOK * TOPK];
__device__ int    g_pairtok[NPAIR];
__device__ float  g_pairw  [NPAIR];
__device__ int    g_tokpair[T_TOK * TOPK];
__device__ float  g_c[T_TOK];

// fp16-preconverted operands
__device__ __half g_xh  [(size_t)T_TOK * HDIM];
__device__ __half g_wgh [(size_t)FB * HDIM];
__device__ __half g_wuh [(size_t)FB * HDIM];
__device__ __half g_wdh [(size_t)HDIM * FB];
__device__ __half g_wegh[(size_t)NE * FE * HDIM];
__device__ __half g_weuh[(size_t)NE * FE * HDIM];
__device__ __half g_wedh[(size_t)NE * HDIM * FE];

// ---------------- helpers ----------------
__device__ __forceinline__ uint32_t smem_u32(const void* p) {
    uint32_t a;
    asm("{ .reg .u64 t; cvta.to.shared.u64 t, %1; cvt.u32.u64 %0, t; }" : "=r"(a) : "l"(p));
    return a;
}
__device__ __forceinline__ void mma_f16(float c[4], const uint32_t a[4], const uint32_t b[2]) {
    asm volatile(
        "mma.sync.aligned.m16n8k16.row.col.f32.f16.f16.f32 "
        "{%0,%1,%2,%3}, {%4,%5,%6,%7}, {%8,%9}, {%0,%1,%2,%3};\n"
        : "+f"(c[0]), "+f"(c[1]), "+f"(c[2]), "+f"(c[3])
        : "r"(a[0]), "r"(a[1]), "r"(a[2]), "r"(a[3]), "r"(b[0]), "r"(b[1]));
}
#define LDSM_X4(r, addr) \
    asm volatile("ldmatrix.sync.aligned.m8n8.x4.shared.b16 {%0,%1,%2,%3}, [%4];" \
        : "=r"((r)[0]), "=r"((r)[1]), "=r"((r)[2]), "=r"((r)[3]) : "r"(addr))
#define CP_ASYNC16(dst, src, sz) \
    asm volatile("cp.async.cg.shared.global [%0], [%1], 16, %2;" \
        :: "r"(dst), "l"(src), "r"(sz) : "memory")
#define CP_COMMIT() asm volatile("cp.async.commit_group;" ::: "memory")
#define CP_WAIT1()  asm volatile("cp.async.wait_group 1;" ::: "memory")

// ---------------- batched fp32->fp16 conversion prepass ----------------
struct CvtArgs {
    const float* src[7];
    __half* dst[7];
    int n4[7];   // count of 4-element groups
};
__global__ void cvt_all_kernel(CvtArgs a) {
    int seg = blockIdx.y;
    const float4* src = reinterpret_cast<const float4*>(a.src[seg]);
    __half2* dst = reinterpret_cast<__half2*>(a.dst[seg]);
    int n4 = a.n4[seg];
    int stride = gridDim.x * blockDim.x;
    for (int i = blockIdx.x * blockDim.x + threadIdx.x; i < n4; i += stride) {
        float4 v = src[i];
        __half2 h0 = __floats2half2_rn(v.x, v.y);
        __half2 h1 = __floats2half2_rn(v.z, v.w);
        dst[2 * i + 0] = h0;
        dst[2 * i + 1] = h1;
    }
}

// ---------------- small kernels (fp32-exact routing) ----------------
__global__ void zero_counts_kernel() {
    int i = threadIdx.x;
    if (i < NE) g_cnt[i] = 0;
}

__global__ void router_kernel(const float* __restrict__ x,
                              const float* __restrict__ rw,
                              const float* __restrict__ alpha) {
    int t = blockIdx.x;
    int tid = threadIdx.x;
    int w = tid >> 5;
    int lane = tid & 31;
    __shared__ float lg[NE];

    float s = 0.f;
    const float* xr = x + (size_t)t * HDIM;
    const float* wr = rw + (size_t)w * HDIM;
    for (int h = lane; h < HDIM; h += 32) s += xr[h] * wr[h];
    #pragma unroll
    for (int o = 16; o > 0; o >>= 1) s += __shfl_down_sync(0xffffffffu, s, o);
    if (lane == 0) lg[w] = s;
    __syncthreads();

    if (tid == 0) {
        float v0 = -1e30f, v1 = -1e30f;
        int i0 = 0, i1 = 0;
        #pragma unroll
        for (int e = 0; e < NE; e++) {
            float v = lg[e];
            if (v > v0) { v1 = v0; i1 = i0; v0 = v; i0 = e; }
            else if (v > v1) { v1 = v; i1 = e; }
        }
        float e1 = expf(v1 - v0);
        float inv = 1.f / (1.f + e1);
        float wa0 = inv * alpha[i0];
        float wa1 = e1 * inv * alpha[i1];
        g_tokexp[2 * t + 0] = i0;
        g_tokexp[2 * t + 1] = i1;
        g_tokw[2 * t + 0] = wa0;
        g_tokw[2 * t + 1] = wa1;
        g_c[t] = 1.f - wa0 - wa1;
        atomicAdd(&g_cnt[i0], 1);
        atomicAdd(&g_cnt[i1], 1);
    }
}

__global__ void scan_kernel() {
    if (threadIdx.x == 0) {
        int acc = 0;
        for (int e = 0; e < NE; e++) {
            g_off[e] = acc;
            g_cur[e] = acc;
            acc += g_cnt[e];
        }
        g_off[NE] = acc;
    }
}

__global__ void scatter_kernel() {
    int t = blockIdx.x * blockDim.x + threadIdx.x;
    if (t >= T_TOK) return;
    #pragma unroll
    for (int s = 0; s < TOPK; s++) {
        int e = g_tokexp[2 * t + s];
        int pos = atomicAdd(&g_cur[e], 1);
        g_pairtok[pos] = t;
        g_pairw[pos] = g_tokw[2 * t + s];
        g_tokpair[2 * t + s] = pos;
    }
}

// ---------------- fp16 m16n8k16 GEMM, cp.async 3-stage, BM=BN=128, BK=64 ----------
// C[m,n] = sum_k A[m,k]*B[n,k]; A,B fp16 (rows 64 halves = 128B), fp32 accumulate.
// Swizzle: chunk c (16B) of row r at byte r*128 + ((c ^ (r&7))<<4).
// MODE 0: C=acc (fp32); MODE 1: C=silu(aux)*acc (fp16 out); MODE 2: C=acc*rowscale (fp32)
// GROUPED: blockIdx.z = expert; GATHER: A row = gidx[global_row]
#define TILE_B 16384                  // 128 rows x 128B (fp16 BK=64)
#define STAGE_B (2 * TILE_B)          // A + B = 32KB
#define NSTAGE 3
#define SMEM_TOTAL (NSTAGE * STAGE_B) // 96KB

template <int MODE, bool GROUPED, bool GATHER>
__global__ void __launch_bounds__(256, 2)
gemm_h(const __half* __restrict__ A,
       const __half* __restrict__ Bb,
       void* __restrict__ Cv,
       const float* __restrict__ aux,
       const float* __restrict__ rowscale,
       const int* __restrict__ offs,
       const int* __restrict__ gidx,
       int M, int N, int K) {
    extern __shared__ __align__(128) char smem[];

    int rstart, rend;
    const __half* B = Bb;
    if (GROUPED) {
        int e = blockIdx.z;
        rstart = offs[e];
        rend = offs[e + 1];
        B += (size_t)e * N * K;
    } else {
        rstart = 0;
        rend = M;
    }
    int rowBase = rstart + blockIdx.y * 128;
    if (rowBase >= rend) return;
    int colBase = blockIdx.x * 128;

    uint32_t sb = smem_u32(smem);
    int tid = threadIdx.x;
    int wid = tid >> 5, lane = tid & 31;
    int warp_m = wid & 1;     // 2 warps over M (64 rows)
    int warp_n = wid >> 1;    // 4 warps over N (32 cols)
    int g = lane >> 2, tg = lane & 3;

    // loader: 4 chunks of 16B per thread per tile (1024 chunks, 256 threads)
    int lrow[4], lc[4], aidx[4];
    uint32_t soff[4], asz[4];
    #pragma unroll
    for (int j = 0; j < 4; j++) {
        int f = tid + j * 256;
        lrow[j] = f >> 3;
        lc[j] = f & 7;
        soff[j] = (uint32_t)(lrow[j] * 128 + ((lc[j] ^ (lrow[j] & 7)) << 4));
        int grow = rowBase + lrow[j];
        bool v = (grow < rend);
        asz[j] = v ? 16u : 0u;
        aidx[j] = v ? (GATHER ? gidx[grow] : grow) : 0;
    }

    // ldmatrix lane address components (canonical fp16 m16n8k16)
    int la7 = lane & 7;
    int lm = lane >> 3;               // matrix index 0..3
    // A x4: matrices (r0-7,k0), (r8-15,k0), (r0-7,k1), (r8-15,k1)
    int a_roff = (lm & 1) * 8 + la7;
    int a_csel = lm >> 1;
    // B x4: matrices (n0-7,k0), (n0-7,k1), (n8-15,k0), (n8-15,k1)
    int b_roff = (lm >> 1) * 8 + la7;
    int b_csel = lm & 1;

    float acc[4][4][4];
    #pragma unroll
    for (int mt = 0; mt < 4; mt++)
        #pragma unroll
        for (int nt = 0; nt < 4; nt++)
            #pragma unroll
            for (int r = 0; r < 4; r++) acc[mt][nt][r] = 0.f;

    int NC = K / 64;

    auto issue = [&](int stage, int k0) {
        uint32_t abase = sb + stage * STAGE_B;
        uint32_t bbase = abase + TILE_B;
        #pragma unroll
        for (int j = 0; j < 4; j++) {
            const __half* src = A + (size_t)aidx[j] * K + k0 + lc[j] * 8;
            CP_ASYNC16(abase + soff[j], src, asz[j]);
        }
        #pragma unroll
        for (int j = 0; j < 4; j++) {
            const __half* src = B + (size_t)(colBase + lrow[j]) * K + k0 + lc[j] * 8;
            CP_ASYNC16(bbase + soff[j], src, 16u);
        }
    };

    issue(0, 0);
    CP_COMMIT();
    if (NC > 1) issue(1, 64);
    CP_COMMIT();

    for (int i = 0; i < NC; i++) {
        CP_WAIT1();
        __syncthreads();
        if (i + 2 < NC) issue((i + 2) % NSTAGE, (i + 2) * 64);
        CP_COMMIT();

        uint32_t abase = sb + (i % NSTAGE) * STAGE_B;
        uint32_t bbase = abase + TILE_B;
        #pragma unroll
        for (int ks = 0; ks < 4; ks++) {       // 4 k16 steps per chunk
            uint32_t af[4][4], bf2[2][4];
            #pragma unroll
            for (int mt = 0; mt < 4; mt++) {
                int row = warp_m * 64 + mt * 16 + a_roff;
                int c = ks * 2 + a_csel;
                uint32_t addr = abase + (uint32_t)(row * 128 + ((c ^ (row & 7)) << 4));
                LDSM_X4(af[mt], addr);
            }
            #pragma unroll
            for (int np = 0; np < 2; np++) {
                int row = warp_n * 32 + np * 16 + b_roff;
                int c = ks * 2 + b_csel;
                uint32_t addr = bbase + (uint32_t)(row * 128 + ((c ^ (row & 7)) << 4));
                LDSM_X4(bf2[np], addr);
            }
            #pragma unroll
            for (int mt = 0; mt < 4; mt++)
                #pragma unroll
                for (int nt = 0; nt < 4; nt++)
                    mma_f16(acc[mt][nt], af[mt], &bf2[nt >> 1][(nt & 1) * 2]);
        }
    }

    // epilogue
    #pragma unroll
    for (int mt = 0; mt < 4; mt++) {
        #pragma unroll
        for (int half_i = 0; half_i < 2; half_i++) {
            int grow = rowBase + warp_m * 64 + mt * 16 + g + half_i * 8;
            if (grow >= rend) continue;
            float rs = (MODE == 2) ? rowscale[grow] : 0.f;
            #pragma unroll
            for (int nt = 0; nt < 4; nt++) {
                int col = colBase + warp_n * 32 + nt * 8 + tg * 2;
                size_t idx = (size_t)grow * N + col;
                float v0 = acc[mt][nt][half_i * 2 + 0];
                float v1 = acc[mt][nt][half_i * 2 + 1];
                if (MODE == 0) {
                    *reinterpret_cast<float2*>(reinterpret_cast<float*>(Cv) + idx) =
                        make_float2(v0, v1);
                } else if (MODE == 1) {
                    float2 gg = *reinterpret_cast<const float2*>(aux + idx);
                    float s0 = gg.x / (1.f + __expf(-gg.x));
                    float s1 = gg.y / (1.f + __expf(-gg.y));
                    *reinterpret_cast<__half2*>(reinterpret_cast<__half*>(Cv) + idx) =
                        __floats2half2_rn(s0 * v0, s1 * v1);
                } else {
                    *reinterpret_cast<float2*>(reinterpret_cast<float*>(Cv) + idx) =
                        make_float2(rs * v0, rs * v1);
                }
            }
        }
    }
}

// ---------------- combine ----------------
__global__ void combine_kernel(float* __restrict__ out) {
    int t = blockIdx.x;
    int i = threadIdx.x;  // 0..511 (H/4)
    int p0 = g_tokpair[2 * t + 0];
    int p1 = g_tokpair[2 * t + 1];
    float ct = g_c[t];
    const float4* b4 = reinterpret_cast<const float4*>(g_base) + (size_t)t * (HDIM / 4);
    const float4* q0 = reinterpret_cast<const float4*>(g_pout) + (size_t)p0 * (HDIM / 4);
    const float4* q1 = reinterpret_cast<const float4*>(g_pout) + (size_t)p1 * (HDIM / 4);
    float4 b = b4[i], a0 = q0[i], a1 = q1[i];
    float4 r;
    r.x = ct * b.x + a0.x + a1.x;
    r.y = ct * b.y + a0.y + a1.y;
    r.z = ct * b.z + a0.z + a1.z;
    r.w = ct * b.w + a0.w + a1.w;
    reinterpret_cast<float4*>(out)[(size_t)t * (HDIM / 4) + i] = r;
}

// ---------------- launch ----------------
extern "C" void kernel_launch(void* const* d_in, const int* in_sizes, int n_in,
                              void* d_out, int out_size) {
    const float* x   = (const float*)d_in[0];
    const float* wg  = (const float*)d_in[1];
    const float* wu  = (const float*)d_in[2];
    const float* wd  = (const float*)d_in[3];
    const float* rw  = (const float*)d_in[4];
    const float* weg = (const float*)d_in[5];
    const float* weu = (const float*)d_in[6];
    const float* wed = (const float*)d_in[7];
    const float* alp = (const float*)d_in[8];
    float* out = (float*)d_out;

    float *pG, *pBase, *pEG, *pPout, *pPairw;
    __half *pHbh, *pHEh, *pXh, *pWgh, *pWuh, *pWdh, *pWegh, *pWeuh, *pWedh;
    int *pOff, *pPairtok;
    cudaGetSymbolAddress((void**)&pG, g_G);
    cudaGetSymbolAddress((void**)&pHbh, g_Hbh);
    cudaGetSymbolAddress((void**)&pBase, g_base);
    cudaGetSymbolAddress((void**)&pEG, g_EG);
    cudaGetSymbolAddress((void**)&pHEh, g_HEh);
    cudaGetSymbolAddress((void**)&pPout, g_pout);
    cudaGetSymbolAddress((void**)&pPairw, g_pairw);
    cudaGetSymbolAddress((void**)&pOff, g_off);
    cudaGetSymbolAddress((void**)&pPairtok, g_pairtok);
    cudaGetSymbolAddress((void**)&pXh, g_xh);
    cudaGetSymbolAddress((void**)&pWgh, g_wgh);
    cudaGetSymbolAddress((void**)&pWuh, g_wuh);
    cudaGetSymbolAddress((void**)&pWdh, g_wdh);
    cudaGetSymbolAddress((void**)&pWegh, g_wegh);
    cudaGetSymbolAddress((void**)&pWeuh, g_weuh);
    cudaGetSymbolAddress((void**)&pWedh, g_wedh);

    cudaFuncSetAttribute(gemm_h<0, false, false>, cudaFuncAttributeMaxDynamicSharedMemorySize, SMEM_TOTAL);
    cudaFuncSetAttribute(gemm_h<1, false, false>, cudaFuncAttributeMaxDynamicSharedMemorySize, SMEM_TOTAL);
    cudaFuncSetAttribute(gemm_h<0, true, true>,   cudaFuncAttributeMaxDynamicSharedMemorySize, SMEM_TOTAL);
    cudaFuncSetAttribute(gemm_h<1, true, true>,   cudaFuncAttributeMaxDynamicSharedMemorySize, SMEM_TOTAL);
    cudaFuncSetAttribute(gemm_h<2, true, false>,  cudaFuncAttributeMaxDynamicSharedMemorySize, SMEM_TOTAL);

    // 0) batched fp32->fp16 prepass (one launch)
    {
        CvtArgs a;
        a.src[0] = x;   a.dst[0] = pXh;   a.n4[0] = (T_TOK * HDIM) / 4;
        a.src[1] = wg;  a.dst[1] = pWgh;  a.n4[1] = (FB * HDIM) / 4;
        a.src[2] = wu;  a.dst[2] = pWuh;  a.n4[2] = (FB * HDIM) / 4;
        a.src[3] = wd;  a.dst[3] = pWdh;  a.n4[3] = (HDIM * FB) / 4;
        a.src[4] = weg; a.dst[4] = pWegh; a.n4[4] = (NE * FE * HDIM) / 4;
        a.src[5] = weu; a.dst[5] = pWeuh; a.n4[5] = (NE * FE * HDIM) / 4;
        a.src[6] = wed; a.dst[6] = pWedh; a.n4[6] = (NE * HDIM * FE) / 4;
        dim3 grid(296, 7, 1);
        cvt_all_kernel<<<grid, 256>>>(a);
    }

    // 1) routing (fp32-exact, original x)
    zero_counts_kernel<<<1, 32>>>();
    router_kernel<<<T_TOK, 256>>>(x, rw, alp);
    scan_kernel<<<1, 1>>>();
    scatter_kernel<<<T_TOK / 256, 256>>>();

    // 2) base MLP
    dim3 gBaseFF(FB / 128, T_TOK / 128, 1);
    gemm_h<0, false, false><<<gBaseFF, 256, SMEM_TOTAL>>>(pXh, pWgh, pG, nullptr, nullptr, nullptr, nullptr,
                                                          T_TOK, FB, HDIM);
    gemm_h<1, false, false><<<gBaseFF, 256, SMEM_TOTAL>>>(pXh, pWuh, pHbh, pG, nullptr, nullptr, nullptr,
                                                          T_TOK, FB, HDIM);
    dim3 gBaseDown(HDIM / 128, T_TOK / 128, 1);
    gemm_h<0, false, false><<<gBaseDown, 256, SMEM_TOTAL>>>(pHbh, pWdh, pBase, nullptr, nullptr, nullptr, nullptr,
                                                            T_TOK, HDIM, FB);

    // 3) expert MLPs (grouped, gathered)
    dim3 gExpFF(FE / 128, 16, NE);
    gemm_h<0, true, true><<<gExpFF, 256, SMEM_TOTAL>>>(pXh, pWegh, pEG, nullptr, nullptr, pOff, pPairtok,
                                                       NPAIR, FE, HDIM);
    gemm_h<1, true, true><<<gExpFF, 256, SMEM_TOTAL>>>(pXh, pWeuh, pHEh, pEG, nullptr, pOff, pPairtok,
                                                       NPAIR, FE, HDIM);
    dim3 gExpDown(HDIM / 128, 16, NE);
    gemm_h<2, true, false><<<gExpDown, 256, SMEM_TOTAL>>>(pHEh, pWedh, pPout, nullptr, pPairw, pOff, nullptr,
                                                          NPAIR, HDIM, FE);

    // 4) combine
    combine_kernel<<<T_TOK, HDIM / 4>>>(out);
}

// round 16
// speedup vs baseline: 1.9746x; 1.0346x over previous
#include <cuda_runtime.h>
#include <cuda_fp16.h>
#include <math.h>
#include <stdint.h>

// ---------------- problem constants ----------------
#define T_TOK 2048
#define HDIM  2048
#define FB    8192
#define NE    8
#define FE    1024
#define TOPK  2
#define NPAIR (T_TOK * TOPK)

// ---------------- scratch ----------------
__device__ __half g_Hbh [(size_t)T_TOK * FB];     // base hidden (fp16)
__device__ float  g_base[(size_t)T_TOK * HDIM];
__device__ __half g_HEh [(size_t)NPAIR * FE];     // expert hidden (fp16)
__device__ float  g_pout[(size_t)NPAIR * HDIM];
__device__ int    g_cnt[NE];
__device__ int    g_off[NE + 1];
__device__ int    g_cur[NE];
__device__ int    g_tokexp[T_TOK * TOPK];
__device__ float  g_tokw  [T_TOK * TOPK];
__device__ int    g_pairtok[NPAIR];
__device__ float  g_pairw  [NPAIR];
__device__ int    g_tokpair[T_TOK * TOPK];
__device__ float  g_c[T_TOK];

// fp16-preconverted operands
__device__ __half g_xh  [(size_t)T_TOK * HDIM];
__device__ __half g_wgh [(size_t)FB * HDIM];
__device__ __half g_wuh [(size_t)FB * HDIM];
__device__ __half g_wdh [(size_t)HDIM * FB];
__device__ __half g_wegh[(size_t)NE * FE * HDIM];
__device__ __half g_weuh[(size_t)NE * FE * HDIM];
__device__ __half g_wedh[(size_t)NE * HDIM * FE];

// ---------------- helpers ----------------
__device__ __forceinline__ uint32_t smem_u32(const void* p) {
    uint32_t a;
    asm("{ .reg .u64 t; cvta.to.shared.u64 t, %1; cvt.u32.u64 %0, t; }" : "=r"(a) : "l"(p));
    return a;
}
__device__ __forceinline__ void mma_f16(float c[4], const uint32_t a[4], const uint32_t b[2]) {
    asm volatile(
        "mma.sync.aligned.m16n8k16.row.col.f32.f16.f16.f32 "
        "{%0,%1,%2,%3}, {%4,%5,%6,%7}, {%8,%9}, {%0,%1,%2,%3};\n"
        : "+f"(c[0]), "+f"(c[1]), "+f"(c[2]), "+f"(c[3])
        : "r"(a[0]), "r"(a[1]), "r"(a[2]), "r"(a[3]), "r"(b[0]), "r"(b[1]));
}
#define LDSM_X4(r, addr) \
    asm volatile("ldmatrix.sync.aligned.m8n8.x4.shared.b16 {%0,%1,%2,%3}, [%4];" \
        : "=r"((r)[0]), "=r"((r)[1]), "=r"((r)[2]), "=r"((r)[3]) : "r"(addr))
#define CP_ASYNC16(dst, src, sz) \
    asm volatile("cp.async.cg.shared.global [%0], [%1], 16, %2;" \
        :: "r"(dst), "l"(src), "r"(sz) : "memory")
#define CP_COMMIT() asm volatile("cp.async.commit_group;" ::: "memory")
#define CP_WAIT1()  asm volatile("cp.async.wait_group 1;" ::: "memory")

// ---------------- batched fp32->fp16 conversion prepass ----------------
struct CvtArgs {
    const float* src[7];
    __half* dst[7];
    int n4[7];
};
__global__ void cvt_all_kernel(CvtArgs a) {
    int seg = blockIdx.y;
    const float4* src = reinterpret_cast<const float4*>(a.src[seg]);
    __half2* dst = reinterpret_cast<__half2*>(a.dst[seg]);
    int n4 = a.n4[seg];
    int stride = gridDim.x * blockDim.x;
    for (int i = blockIdx.x * blockDim.x + threadIdx.x; i < n4; i += stride) {
        float4 v = src[i];
        dst[2 * i + 0] = __floats2half2_rn(v.x, v.y);
        dst[2 * i + 1] = __floats2half2_rn(v.z, v.w);
    }
}

// ---------------- small kernels (fp32-exact routing) ----------------
__global__ void zero_counts_kernel() {
    int i = threadIdx.x;
    if (i < NE) g_cnt[i] = 0;
}

__global__ void router_kernel(const float* __restrict__ x,
                              const float* __restrict__ rw,
                              const float* __restrict__ alpha) {
    int t = blockIdx.x;
    int tid = threadIdx.x;
    int w = tid >> 5;
    int lane = tid & 31;
    __shared__ float lg[NE];

    float s = 0.f;
    const float* xr = x + (size_t)t * HDIM;
    const float* wr = rw + (size_t)w * HDIM;
    for (int h = lane; h < HDIM; h += 32) s += xr[h] * wr[h];
    #pragma unroll
    for (int o = 16; o > 0; o >>= 1) s += __shfl_down_sync(0xffffffffu, s, o);
    if (lane == 0) lg[w] = s;
    __syncthreads();

    if (tid == 0) {
        float v0 = -1e30f, v1 = -1e30f;
        int i0 = 0, i1 = 0;
        #pragma unroll
        for (int e = 0; e < NE; e++) {
            float v = lg[e];
            if (v > v0) { v1 = v0; i1 = i0; v0 = v; i0 = e; }
            else if (v > v1) { v1 = v; i1 = e; }
        }
        float e1 = expf(v1 - v0);
        float inv = 1.f / (1.f + e1);
        float wa0 = inv * alpha[i0];
        float wa1 = e1 * inv * alpha[i1];
        g_tokexp[2 * t + 0] = i0;
        g_tokexp[2 * t + 1] = i1;
        g_tokw[2 * t + 0] = wa0;
        g_tokw[2 * t + 1] = wa1;
        g_c[t] = 1.f - wa0 - wa1;
        atomicAdd(&g_cnt[i0], 1);
        atomicAdd(&g_cnt[i1], 1);
    }
}

__global__ void scan_kernel() {
    if (threadIdx.x == 0) {
        int acc = 0;
        for (int e = 0; e < NE; e++) {
            g_off[e] = acc;
            g_cur[e] = acc;
            acc += g_cnt[e];
        }
        g_off[NE] = acc;
    }
}

__global__ void scatter_kernel() {
    int t = blockIdx.x * blockDim.x + threadIdx.x;
    if (t >= T_TOK) return;
    #pragma unroll
    for (int s = 0; s < TOPK; s++) {
        int e = g_tokexp[2 * t + s];
        int pos = atomicAdd(&g_cur[e], 1);
        g_pairtok[pos] = t;
        g_pairw[pos] = g_tokw[2 * t + s];
        g_tokpair[2 * t + s] = pos;
    }
}

// ---------------- shared GEMM config ----------------
#define TILE_B 16384                  // 128 rows x 128B (fp16 BK=64)
#define STAGE_B (2 * TILE_B)          // A + B = 32KB
#define NSTAGE 3
#define SMEM_TOTAL (NSTAGE * STAGE_B) // 96KB
#define SG_STRIDE 66                  // gate-staging stride (floats), conflict-free

// ============ FUSED FF GEMM: H[m, n] = silu(x·Wg_n) * (x·Wu_n), fp16 out =========
// B tile rows 0-63 = Wg[colBase64 + r], rows 64-127 = Wu[colBase64 + r] (same n range).
// Output cols per CTA: 64. Grid x = Nout/64.
// GROUPED: blockIdx.z = expert, rows in [off[e], off[e+1]); GATHER: A row = gidx[row].
template <bool GROUPED, bool GATHER>
__global__ void __launch_bounds__(256, 2)
gemm_ff(const __half* __restrict__ A,
        const __half* __restrict__ Bgb,
        const __half* __restrict__ Bub,
        __half* __restrict__ C,
        const int* __restrict__ offs,
        const int* __restrict__ gidx,
        int M, int Nout, int K) {
    extern __shared__ __align__(128) char smem[];

    int rstart, rend;
    const __half* Bg = Bgb;
    const __half* Bu = Bub;
    if (GROUPED) {
        int e = blockIdx.z;
        rstart = offs[e];
        rend = offs[e + 1];
        Bg += (size_t)e * Nout * K;
        Bu += (size_t)e * Nout * K;
    } else {
        rstart = 0;
        rend = M;
    }
    int rowBase = rstart + blockIdx.y * 128;
    if (rowBase >= rend) return;
    int colBase64 = blockIdx.x * 64;

    uint32_t sb = smem_u32(smem);
    int tid = threadIdx.x;
    int wid = tid >> 5, lane = tid & 31;
    int warp_m = wid & 1;
    int warp_n = wid >> 1;    // 0..3: 0-1 gate cols [0,64), 2-3 up cols [0,64)
    int g = lane >> 2, tg = lane & 3;

    // loader: 4 chunks of 16B per thread per tile
    int lrow[4], lc[4], aidx[4];
    uint32_t soff[4], asz[4];
    #pragma unroll
    for (int j = 0; j < 4; j++) {
        int f = tid + j * 256;
        lrow[j] = f >> 3;
        lc[j] = f & 7;
        soff[j] = (uint32_t)(lrow[j] * 128 + ((lc[j] ^ (lrow[j] & 7)) << 4));
        int grow = rowBase + lrow[j];
        bool v = (grow < rend);
        asz[j] = v ? 16u : 0u;
        aidx[j] = v ? (GATHER ? gidx[grow] : grow) : 0;
    }

    int la7 = lane & 7;
    int lm = lane >> 3;
    int a_roff = (lm & 1) * 8 + la7;
    int a_csel = lm >> 1;
    int b_roff = (lm >> 1) * 8 + la7;
    int b_csel = lm & 1;

    float acc[4][4][4];
    #pragma unroll
    for (int mt = 0; mt < 4; mt++)
        #pragma unroll
        for (int nt = 0; nt < 4; nt++)
            #pragma unroll
            for (int r = 0; r < 4; r++) acc[mt][nt][r] = 0.f;

    int NC = K / 64;

    auto issue = [&](int stage, int k0) {
        uint32_t abase = sb + stage * STAGE_B;
        uint32_t bbase = abase + TILE_B;
        #pragma unroll
        for (int j = 0; j < 4; j++) {
            const __half* src = A + (size_t)aidx[j] * K + k0 + lc[j] * 8;
            CP_ASYNC16(abase + soff[j], src, asz[j]);
        }
        #pragma unroll
        for (int j = 0; j < 4; j++) {
            const __half* wsrc = (lrow[j] < 64)
                ? Bg + (size_t)(colBase64 + lrow[j]) * K + k0 + lc[j] * 8
                : Bu + (size_t)(colBase64 + lrow[j] - 64) * K + k0 + lc[j] * 8;
            CP_ASYNC16(bbase + soff[j], wsrc, 16u);
        }
    };

    issue(0, 0);
    CP_COMMIT();
    if (NC > 1) issue(1, 64);
    CP_COMMIT();

    for (int i = 0; i < NC; i++) {
        CP_WAIT1();
        __syncthreads();
        if (i + 2 < NC) issue((i + 2) % NSTAGE, (i + 2) * 64);
        CP_COMMIT();

        uint32_t abase = sb + (i % NSTAGE) * STAGE_B;
        uint32_t bbase = abase + TILE_B;
        #pragma unroll
        for (int ks = 0; ks < 4; ks++) {
            uint32_t af[4][4], bf2[2][4];
            #pragma unroll
            for (int mt = 0; mt < 4; mt++) {
                int row = warp_m * 64 + mt * 16 + a_roff;
                int c = ks * 2 + a_csel;
                uint32_t addr = abase + (uint32_t)(row * 128 + ((c ^ (row & 7)) << 4));
                LDSM_X4(af[mt], addr);
            }
            #pragma unroll
            for (int np = 0; np < 2; np++) {
                int row = warp_n * 32 + np * 16 + b_roff;
                int c = ks * 2 + b_csel;
                uint32_t addr = bbase + (uint32_t)(row * 128 + ((c ^ (row & 7)) << 4));
                LDSM_X4(bf2[np], addr);
            }
            #pragma unroll
            for (int mt = 0; mt < 4; mt++)
                #pragma unroll
                for (int nt = 0; nt < 4; nt++)
                    mma_f16(acc[mt][nt], af[mt], &bf2[nt >> 1][(nt & 1) * 2]);
        }
    }

    // fused epilogue: gate warps stage -> smem; up warps combine -> fp16 C
    __syncthreads();   // all stage reads done; safe to reuse pipeline smem
    float* sgate = reinterpret_cast<float*>(smem);   // 128 x SG_STRIDE floats = 33.8KB
    if (warp_n < 2) {
        #pragma unroll
        for (int mt = 0; mt < 4; mt++)
            #pragma unroll
            for (int half_i = 0; half_i < 2; half_i++) {
                int rloc = warp_m * 64 + mt * 16 + g + half_i * 8;
                #pragma unroll
                for (int nt = 0; nt < 4; nt++) {
                    int cloc = warp_n * 32 + nt * 8 + tg * 2;
                    sgate[rloc * SG_STRIDE + cloc]     = acc[mt][nt][half_i * 2 + 0];
                    sgate[rloc * SG_STRIDE + cloc + 1] = acc[mt][nt][half_i * 2 + 1];
                }
            }
    }
    __syncthreads();
    if (warp_n >= 2) {
        #pragma unroll
        for (int mt = 0; mt < 4; mt++)
            #pragma unroll
            for (int half_i = 0; half_i < 2; half_i++) {
                int rloc = warp_m * 64 + mt * 16 + g + half_i * 8;
                int grow = rowBase + rloc;
                if (grow >= rend) continue;
                #pragma unroll
                for (int nt = 0; nt < 4; nt++) {
                    int cloc = (warp_n - 2) * 32 + nt * 8 + tg * 2;
                    float g0 = sgate[rloc * SG_STRIDE + cloc];
                    float g1 = sgate[rloc * SG_STRIDE + cloc + 1];
                    float u0 = acc[mt][nt][half_i * 2 + 0];
                    float u1 = acc[mt][nt][half_i * 2 + 1];
                    float h0 = g0 / (1.f + __expf(-g0)) * u0;
                    float h1 = g1 / (1.f + __expf(-g1)) * u1;
                    size_t idx = (size_t)grow * Nout + colBase64 + cloc;
                    *reinterpret_cast<__half2*>(C + idx) = __floats2half2_rn(h0, h1);
                }
            }
    }
}

// ============ plain fp16 GEMM for down projections ============
// MODE 0: C=acc (fp32); MODE 2: C=acc*rowscale[row] (fp32)
template <int MODE, bool GROUPED>
__global__ void __launch_bounds__(256, 2)
gemm_h(const __half* __restrict__ A,
       const __half* __restrict__ Bb,
       float* __restrict__ C,
       const float* __restrict__ rowscale,
       const int* __restrict__ offs,
       int M, int N, int K) {
    extern __shared__ __align__(128) char smem[];

    int rstart, rend;
    const __half* B = Bb;
    if (GROUPED) {
        int e = blockIdx.z;
        rstart = offs[e];
        rend = offs[e + 1];
        B += (size_t)e * N * K;
    } else {
        rstart = 0;
        rend = M;
    }
    int rowBase = rstart + blockIdx.y * 128;
    if (rowBase >= rend) return;
    int colBase = blockIdx.x * 128;

    uint32_t sb = smem_u32(smem);
    int tid = threadIdx.x;
    int wid = tid >> 5, lane = tid & 31;
    int warp_m = wid & 1;
    int warp_n = wid >> 1;
    int g = lane >> 2, tg = lane & 3;

    int lrow[4], lc[4], aidx[4];
    uint32_t soff[4], asz[4];
    #pragma unroll
    for (int j = 0; j < 4; j++) {
        int f = tid + j * 256;
        lrow[j] = f >> 3;
        lc[j] = f & 7;
        soff[j] = (uint32_t)(lrow[j] * 128 + ((lc[j] ^ (lrow[j] & 7)) << 4));
        int grow = rowBase + lrow[j];
        bool v = (grow < rend);
        asz[j] = v ? 16u : 0u;
        aidx[j] = v ? grow : 0;
    }

    int la7 = lane & 7;
    int lm = lane >> 3;
    int a_roff = (lm & 1) * 8 + la7;
    int a_csel = lm >> 1;
    int b_roff = (lm >> 1) * 8 + la7;
    int b_csel = lm & 1;

    float acc[4][4][4];
    #pragma unroll
    for (int mt = 0; mt < 4; mt++)
        #pragma unroll
        for (int nt = 0; nt < 4; nt++)
            #pragma unroll
            for (int r = 0; r < 4; r++) acc[mt][nt][r] = 0.f;

    int NC = K / 64;

    auto issue = [&](int stage, int k0) {
        uint32_t abase = sb + stage * STAGE_B;
        uint32_t bbase = abase + TILE_B;
        #pragma unroll
        for (int j = 0; j < 4; j++) {
            const __half* src = A + (size_t)aidx[j] * K + k0 + lc[j] * 8;
            CP_ASYNC16(abase + soff[j], src, asz[j]);
        }
        #pragma unroll
        for (int j = 0; j < 4; j++) {
            const __half* src = B + (size_t)(colBase + lrow[j]) * K + k0 + lc[j] * 8;
            CP_ASYNC16(bbase + soff[j], src, 16u);
        }
    };

    issue(0, 0);
    CP_COMMIT();
    if (NC > 1) issue(1, 64);
    CP_COMMIT();

    for (int i = 0; i < NC; i++) {
        CP_WAIT1();
        __syncthreads();
        if (i + 2 < NC) issue((i + 2) % NSTAGE, (i + 2) * 64);
        CP_COMMIT();

        uint32_t abase = sb + (i % NSTAGE) * STAGE_B;
        uint32_t bbase = abase + TILE_B;
        #pragma unroll
        for (int ks = 0; ks < 4; ks++) {
            uint32_t af[4][4], bf2[2][4];
            #pragma unroll
            for (int mt = 0; mt < 4; mt++) {
                int row = warp_m * 64 + mt * 16 + a_roff;
                int c = ks * 2 + a_csel;
                uint32_t addr = abase + (uint32_t)(row * 128 + ((c ^ (row & 7)) << 4));
                LDSM_X4(af[mt], addr);
            }
            #pragma unroll
            for (int np = 0; np < 2; np++) {
                int row = warp_n * 32 + np * 16 + b_roff;
                int c = ks * 2 + b_csel;
                uint32_t addr = bbase + (uint32_t)(row * 128 + ((c ^ (row & 7)) << 4));
                LDSM_X4(bf2[np], addr);
            }
            #pragma unroll
            for (int mt = 0; mt < 4; mt++)
                #pragma unroll
                for (int nt = 0; nt < 4; nt++)
                    mma_f16(acc[mt][nt], af[mt], &bf2[nt >> 1][(nt & 1) * 2]);
        }
    }

    #pragma unroll
    for (int mt = 0; mt < 4; mt++) {
        #pragma unroll
        for (int half_i = 0; half_i < 2; half_i++) {
            int grow = rowBase + warp_m * 64 + mt * 16 + g + half_i * 8;
            if (grow >= rend) continue;
            float rs = (MODE == 2) ? rowscale[grow] : 0.f;
            #pragma unroll
            for (int nt = 0; nt < 4; nt++) {
                int col = colBase + warp_n * 32 + nt * 8 + tg * 2;
                size_t idx = (size_t)grow * N + col;
                float v0 = acc[mt][nt][half_i * 2 + 0];
                float v1 = acc[mt][nt][half_i * 2 + 1];
                float2 r = (MODE == 2) ? make_float2(rs * v0, rs * v1)
                                       : make_float2(v0, v1);
                *reinterpret_cast<float2*>(C + idx) = r;
            }
        }
    }
}

// ---------------- combine ----------------
__global__ void combine_kernel(float* __restrict__ out) {
    int t = blockIdx.x;
    int i = threadIdx.x;  // 0..511 (H/4)
    int p0 = g_tokpair[2 * t + 0];
    int p1 = g_tokpair[2 * t + 1];
    float ct = g_c[t];
    const float4* b4 = reinterpret_cast<const float4*>(g_base) + (size_t)t * (HDIM / 4);
    const float4* q0 = reinterpret_cast<const float4*>(g_pout) + (size_t)p0 * (HDIM / 4);
    const float4* q1 = reinterpret_cast<const float4*>(g_pout) + (size_t)p1 * (HDIM / 4);
    float4 b = b4[i], a0 = q0[i], a1 = q1[i];
    float4 r;
    r.x = ct * b.x + a0.x + a1.x;
    r.y = ct * b.y + a0.y + a1.y;
    r.z = ct * b.z + a0.z + a1.z;
    r.w = ct * b.w + a0.w + a1.w;
    reinterpret_cast<float4*>(out)[(size_t)t * (HDIM / 4) + i] = r;
}

// ---------------- launch ----------------
extern "C" void kernel_launch(void* const* d_in, const int* in_sizes, int n_in,
                              void* d_out, int out_size) {
    const float* x   = (const float*)d_in[0];
    const float* wg  = (const float*)d_in[1];
    const float* wu  = (const float*)d_in[2];
    const float* wd  = (const float*)d_in[3];
    const float* rw  = (const float*)d_in[4];
    const float* weg = (const float*)d_in[5];
    const float* weu = (const float*)d_in[6];
    const float* wed = (const float*)d_in[7];
    const float* alp = (const float*)d_in[8];
    float* out = (float*)d_out;

    float *pBase, *pPout, *pPairw;
    __half *pHbh, *pHEh, *pXh, *pWgh, *pWuh, *pWdh, *pWegh, *pWeuh, *pWedh;
    int *pOff, *pPairtok;
    cudaGetSymbolAddress((void**)&pHbh, g_Hbh);
    cudaGetSymbolAddress((void**)&pBase, g_base);
    cudaGetSymbolAddress((void**)&pHEh, g_HEh);
    cudaGetSymbolAddress((void**)&pPout, g_pout);
    cudaGetSymbolAddress((void**)&pPairw, g_pairw);
    cudaGetSymbolAddress((void**)&pOff, g_off);
    cudaGetSymbolAddress((void**)&pPairtok, g_pairtok);
    cudaGetSymbolAddress((void**)&pXh, g_xh);
    cudaGetSymbolAddress((void**)&pWgh, g_wgh);
    cudaGetSymbolAddress((void**)&pWuh, g_wuh);
    cudaGetSymbolAddress((void**)&pWdh, g_wdh);
    cudaGetSymbolAddress((void**)&pWegh, g_wegh);
    cudaGetSymbolAddress((void**)&pWeuh, g_weuh);
    cudaGetSymbolAddress((void**)&pWedh, g_wedh);

    cudaFuncSetAttribute(gemm_ff<false, false>, cudaFuncAttributeMaxDynamicSharedMemorySize, SMEM_TOTAL);
    cudaFuncSetAttribute(gemm_ff<true, true>,   cudaFuncAttributeMaxDynamicSharedMemorySize, SMEM_TOTAL);
    cudaFuncSetAttribute(gemm_h<0, false>, cudaFuncAttributeMaxDynamicSharedMemorySize, SMEM_TOTAL);
    cudaFuncSetAttribute(gemm_h<2, true>,  cudaFuncAttributeMaxDynamicSharedMemorySize, SMEM_TOTAL);

    // 0) batched fp32->fp16 prepass
    {
        CvtArgs a;
        a.src[0] = x;   a.dst[0] = pXh;   a.n4[0] = (T_TOK * HDIM) / 4;
        a.src[1] = wg;  a.dst[1] = pWgh;  a.n4[1] = (FB * HDIM) / 4;
        a.src[2] = wu;  a.dst[2] = pWuh;  a.n4[2] = (FB * HDIM) / 4;
        a.src[3] = wd;  a.dst[3] = pWdh;  a.n4[3] = (HDIM * FB) / 4;
        a.src[4] = weg; a.dst[4] = pWegh; a.n4[4] = (NE * FE * HDIM) / 4;
        a.src[5] = weu; a.dst[5] = pWeuh; a.n4[5] = (NE * FE * HDIM) / 4;
        a.src[6] = wed; a.dst[6] = pWedh; a.n4[6] = (NE * HDIM * FE) / 4;
        dim3 grid(296, 7, 1);
        cvt_all_kernel<<<grid, 256>>>(a);
    }

    // 1) routing (fp32-exact, original x)
    zero_counts_kernel<<<1, 32>>>();
    router_kernel<<<T_TOK, 256>>>(x, rw, alp);
    scan_kernel<<<1, 1>>>();
    scatter_kernel<<<T_TOK / 256, 256>>>();

    // 2) base MLP: fused gate+up, then down
    dim3 gBaseFF(FB / 64, T_TOK / 128, 1);
    gemm_ff<false, false><<<gBaseFF, 256, SMEM_TOTAL>>>(pXh, pWgh, pWuh, pHbh,
                                                        nullptr, nullptr, T_TOK, FB, HDIM);
    dim3 gBaseDown(HDIM / 128, T_TOK / 128, 1);
    gemm_h<0, false><<<gBaseDown, 256, SMEM_TOTAL>>>(pHbh, pWdh, pBase, nullptr, nullptr,
                                                     T_TOK, HDIM, FB);

    // 3) expert MLPs: fused gate+up (grouped+gathered), then scaled down
    dim3 gExpFF(FE / 64, 16, NE);
    gemm_ff<true, true><<<gExpFF, 256, SMEM_TOTAL>>>(pXh, pWegh, pWeuh, pHEh,
                                                     pOff, pPairtok, NPAIR, FE, HDIM);
    dim3 gExpDown(HDIM / 128, 16, NE);
    gemm_h<2, true><<<gExpDown, 256, SMEM_TOTAL>>>(pHEh, pWedh, pPout, pPairw, pOff,
                                                   NPAIR, HDIM, FE);

    // 4) combine
    combine_kernel<<<T_TOK, HDIM / 4>>>(out);
}